// round 1
// baseline (speedup 1.0000x reference)
#include <cuda_runtime.h>

// ---------------------------------------------------------------------------
// WindowAttention: B=4096 windows, N=64 tokens, C=192, H=6 heads, D=32.
// Pipeline:
//   K1 gemm_bias: qkv = X @ Wqkv + b          [262144 x 576]
//   K2 attn:      per (window, head) attention -> ctx [262144 x 192]
//   K3 gemm_bias: out = ctx @ Wproj + b       [262144 x 192]
// fp32 throughout (rel_err budget 1e-3; fp32 gives ~1e-7).
// ---------------------------------------------------------------------------

#define B_WIN    4096
#define N_TOK    64
#define C_DIM    192
#define H_NUM    6
#define D_HEAD   32
#define QKV_COLS 576
#define NUM_WINS 64
#define QK_SCALE 0.07216878364870323f   // 192^-0.5

// Scratch (device-global arrays: allocation-free per harness rules)
__device__ float g_qkv[(size_t)B_WIN * N_TOK * QKV_COLS];   // ~604 MB
__device__ float g_ctx[(size_t)B_WIN * N_TOK * C_DIM];      // ~201 MB

// ---------------------------------------------------------------------------
// Tiled fp32 GEMM with bias epilogue: C[M,N] = A[M,K] @ B[K,N] + bias[N]
// 64x64 block tile, 256 threads, 4x4 register tile per thread, K-tile 16.
// Requires M%64==0, N%64==0, K%16==0 (holds for both call sites).
// ---------------------------------------------------------------------------
#define GT_M 64
#define GT_N 64
#define GT_K 16

__global__ __launch_bounds__(256) void gemm_bias_kernel(
    const float* __restrict__ A, const float* __restrict__ B,
    const float* __restrict__ bias, float* __restrict__ C,
    int M, int N, int K)
{
    __shared__ float As[GT_K][GT_M];      // stored K-major for inner loop
    __shared__ float Bs[GT_K][GT_N];

    const int tid = threadIdx.x;
    const int tx  = tid & 15;             // 0..15 (cols)
    const int ty  = tid >> 4;             // 0..15 (rows)
    const int m0  = blockIdx.y * GT_M;
    const int n0  = blockIdx.x * GT_N;

    // cooperative load indices
    const int a_row = tid >> 2;           // 0..63
    const int a_k4  = (tid & 3) << 2;     // 0,4,8,12
    const int b_kr  = tid >> 4;           // 0..15
    const int b_nc  = (tid & 15) << 2;    // 0..60

    float acc[4][4];
#pragma unroll
    for (int i = 0; i < 4; i++)
#pragma unroll
        for (int j = 0; j < 4; j++) acc[i][j] = 0.f;

    for (int k0 = 0; k0 < K; k0 += GT_K) {
        float4 av = *reinterpret_cast<const float4*>(
            &A[(size_t)(m0 + a_row) * K + k0 + a_k4]);
        As[a_k4 + 0][a_row] = av.x;
        As[a_k4 + 1][a_row] = av.y;
        As[a_k4 + 2][a_row] = av.z;
        As[a_k4 + 3][a_row] = av.w;

        *reinterpret_cast<float4*>(&Bs[b_kr][b_nc]) =
            *reinterpret_cast<const float4*>(&B[(size_t)(k0 + b_kr) * N + n0 + b_nc]);
        __syncthreads();

#pragma unroll
        for (int kk = 0; kk < GT_K; kk++) {
            float4 a4 = *reinterpret_cast<const float4*>(&As[kk][ty << 2]);
            float4 b4 = *reinterpret_cast<const float4*>(&Bs[kk][tx << 2]);
            float ar[4] = {a4.x, a4.y, a4.z, a4.w};
            float br[4] = {b4.x, b4.y, b4.z, b4.w};
#pragma unroll
            for (int i = 0; i < 4; i++)
#pragma unroll
                for (int j = 0; j < 4; j++)
                    acc[i][j] += ar[i] * br[j];
        }
        __syncthreads();
    }

#pragma unroll
    for (int i = 0; i < 4; i++) {
        const int m = m0 + (ty << 2) + i;
        float* crow = &C[(size_t)m * N + n0 + (tx << 2)];
        const float* brow = &bias[n0 + (tx << 2)];
        float4 o;
        o.x = acc[i][0] + brow[0];
        o.y = acc[i][1] + brow[1];
        o.z = acc[i][2] + brow[2];
        o.w = acc[i][3] + brow[3];
        *reinterpret_cast<float4*>(crow) = o;
    }
}

// ---------------------------------------------------------------------------
// Per-(window, head) attention. grid = (4096, 6), block = 64 threads.
// Thread t owns token row t: scores row, softmax, AV row.
// ---------------------------------------------------------------------------
__global__ __launch_bounds__(64) void attn_kernel(
    const float* __restrict__ mask,
    const float* __restrict__ bias_table)
{
    const int b = blockIdx.x;
    const int h = blockIdx.y;
    const int t = threadIdx.x;            // 0..63

    __shared__ float Ks[64][36];          // pad 36: float4-aligned, conflict-spread
    __shared__ float Vs[64][36];
    __shared__ float Ss[64][65];          // scores, stride 65 = conflict-free
    __shared__ float Bh[225];             // bias_table slice for this head

    const float* base = g_qkv + (size_t)b * N_TOK * QKV_COLS;

    // Load K, V rows for token t into smem
    {
        const float* krow = base + t * QKV_COLS + C_DIM + h * D_HEAD;
        const float* vrow = base + t * QKV_COLS + 2 * C_DIM + h * D_HEAD;
#pragma unroll
        for (int d = 0; d < D_HEAD; d += 4) {
            *reinterpret_cast<float4*>(&Ks[t][d]) =
                *reinterpret_cast<const float4*>(krow + d);
            *reinterpret_cast<float4*>(&Vs[t][d]) =
                *reinterpret_cast<const float4*>(vrow + d);
        }
    }
    // Bias slice for head h: 225 entries
    for (int i = t; i < 225; i += 64)
        Bh[i] = bias_table[i * H_NUM + h];

    // Q row of token t into registers
    float q[D_HEAD];
    {
        const float* qrow = base + t * QKV_COLS + h * D_HEAD;
#pragma unroll
        for (int d = 0; d < D_HEAD; d += 4) {
            float4 qv = *reinterpret_cast<const float4*>(qrow + d);
            q[d] = qv.x; q[d + 1] = qv.y; q[d + 2] = qv.z; q[d + 3] = qv.w;
        }
    }
    __syncthreads();

    const float* mrow = mask + (size_t)(((b & (NUM_WINS - 1)) * N_TOK + t) * N_TOK);
    const int ty = t >> 3, txp = t & 7;

    float mx = -1e30f;
#pragma unroll 4
    for (int j = 0; j < N_TOK; j++) {
        float dot = 0.f;
#pragma unroll
        for (int d = 0; d < D_HEAD; d += 4) {
            float4 kv = *reinterpret_cast<const float4*>(&Ks[j][d]);
            dot += q[d] * kv.x + q[d + 1] * kv.y + q[d + 2] * kv.z + q[d + 3] * kv.w;
        }
        const int idx = (ty - (j >> 3) + 7) * 15 + (txp - (j & 7) + 7);
        const float val = dot * QK_SCALE + Bh[idx] + mrow[j];
        Ss[t][j] = val;
        mx = fmaxf(mx, val);
    }

    float sum = 0.f;
#pragma unroll 8
    for (int j = 0; j < N_TOK; j++) {
        const float e = __expf(Ss[t][j] - mx);
        Ss[t][j] = e;
        sum += e;
    }
    const float inv = 1.f / sum;

    float o[D_HEAD];
#pragma unroll
    for (int d = 0; d < D_HEAD; d++) o[d] = 0.f;

#pragma unroll 4
    for (int j = 0; j < N_TOK; j++) {
        const float p = Ss[t][j];
#pragma unroll
        for (int d = 0; d < D_HEAD; d += 4) {
            float4 vv = *reinterpret_cast<const float4*>(&Vs[j][d]);
            o[d]     += p * vv.x;
            o[d + 1] += p * vv.y;
            o[d + 2] += p * vv.z;
            o[d + 3] += p * vv.w;
        }
    }

    float* orow = g_ctx + ((size_t)b * N_TOK + t) * C_DIM + h * D_HEAD;
#pragma unroll
    for (int d = 0; d < D_HEAD; d += 4) {
        float4 ov = make_float4(o[d] * inv, o[d + 1] * inv,
                                o[d + 2] * inv, o[d + 3] * inv);
        *reinterpret_cast<float4*>(orow + d) = ov;
    }
}

// ---------------------------------------------------------------------------
// Launch
// Inputs (metadata order): inputs, mask, w_qkv, b_qkv, bias_table, w_proj, b_proj
// ---------------------------------------------------------------------------
extern "C" void kernel_launch(void* const* d_in, const int* in_sizes, int n_in,
                              void* d_out, int out_size)
{
    const float* x          = (const float*)d_in[0];
    const float* mask       = (const float*)d_in[1];
    const float* w_qkv      = (const float*)d_in[2];
    const float* b_qkv      = (const float*)d_in[3];
    const float* bias_table = (const float*)d_in[4];
    const float* w_proj     = (const float*)d_in[5];
    const float* b_proj     = (const float*)d_in[6];
    float* out = (float*)d_out;

    float* qkv_ptr = nullptr;
    float* ctx_ptr = nullptr;
    cudaGetSymbolAddress((void**)&qkv_ptr, g_qkv);
    cudaGetSymbolAddress((void**)&ctx_ptr, g_ctx);

    const int M = B_WIN * N_TOK;          // 262144

    // K1: QKV projection  [M,192] @ [192,576]
    {
        dim3 grid(QKV_COLS / GT_N, M / GT_M);
        gemm_bias_kernel<<<grid, 256>>>(x, w_qkv, b_qkv, qkv_ptr,
                                        M, QKV_COLS, C_DIM);
    }
    // K2: attention per (window, head)
    {
        dim3 grid(B_WIN, H_NUM);
        attn_kernel<<<grid, 64>>>(mask, bias_table);
    }
    // K3: output projection  [M,192] @ [192,192]
    {
        dim3 grid(C_DIM / GT_N, M / GT_M);
        gemm_bias_kernel<<<grid, 256>>>(ctx_ptr, w_proj, b_proj, out,
                                        M, C_DIM, C_DIM);
    }
}

// round 4
// speedup vs baseline: 1.7204x; 1.7204x over previous
#include <cuda_runtime.h>
#include <cstdint>

// ---------------------------------------------------------------------------
// WindowAttention: B=4096 windows, N=64 tokens, C=192, H=6 heads, D=32.
//   K1 gemm_tf32: qkv = X @ Wqkv + b          [262144 x 576]   (tensor cores)
//   K2 attn:      per (window, head) attention -> ctx           (fp32 SIMT)
//   K3 gemm_tf32: out = ctx @ Wproj + b       [262144 x 192]   (tensor cores)
// GEMMs use mma.sync.m16n8k8 tf32 with cvt.rna rounding: rel_err ~1e-4.
// ---------------------------------------------------------------------------

#define B_WIN    4096
#define N_TOK    64
#define C_DIM    192
#define H_NUM    6
#define D_HEAD   32
#define QKV_COLS 576
#define NUM_WINS 64
#define QK_SCALE 0.07216878364870323f   // 192^-0.5

__device__ float g_qkv[(size_t)B_WIN * N_TOK * QKV_COLS];
__device__ float g_ctx[(size_t)B_WIN * N_TOK * C_DIM];

// ---------------------------------------------------------------------------
// tf32 tensor-core GEMM: C[M,N] = A[M,K] @ B[K,N] + bias[N]
// Block tile 128x64, BK=32, 256 threads (8 warps, 4x2), warp tile 32x32.
// Requires M%128==0, N%64==0, K%32==0  (holds: K=192, N=576/192, M=262144).
// ---------------------------------------------------------------------------
#define BM 128
#define BN 64
#define BK 32
#define ASTR 36   // pad: frag loads hit banks (4*g + tig) -> conflict-free
#define BSTR 72   // pad: frag loads hit banks (8*tig + g) -> conflict-free

__device__ __forceinline__ uint32_t f2tf(float x) {
    uint32_t y;
    asm("cvt.rna.tf32.f32 %0, %1;" : "=r"(y) : "f"(x));
    return y;
}

__device__ __forceinline__ void mma_tf32(float c[4], const uint32_t a[4],
                                         const uint32_t b[2]) {
    asm volatile(
        "mma.sync.aligned.m16n8k8.row.col.f32.tf32.tf32.f32 "
        "{%0,%1,%2,%3}, {%4,%5,%6,%7}, {%8,%9}, {%0,%1,%2,%3};\n"
        : "+f"(c[0]), "+f"(c[1]), "+f"(c[2]), "+f"(c[3])
        : "r"(a[0]), "r"(a[1]), "r"(a[2]), "r"(a[3]), "r"(b[0]), "r"(b[1]));
}

__global__ __launch_bounds__(256) void gemm_tf32_kernel(
    const float* __restrict__ A, const float* __restrict__ Bm,
    const float* __restrict__ bias, float* __restrict__ C,
    int M, int N, int K)
{
    __shared__ uint32_t As[BM][ASTR];   // 18 KB
    __shared__ uint32_t Bs[BK][BSTR];   //  9 KB

    const int tid  = threadIdx.x;
    const int wid  = tid >> 5;
    const int lane = tid & 31;
    const int gid  = lane >> 2;          // 0..7
    const int tig  = lane & 3;           // 0..3
    const int wm   = (wid >> 1) * 32;    // 0,32,64,96
    const int wn   = (wid & 1) * 32;     // 0,32

    const int m0 = blockIdx.y * BM;
    const int n0 = blockIdx.x * BN;

    // cooperative-load indices
    const int ar = tid >> 3;             // 0..31 (4 row-passes of 32)
    const int ac = (tid & 7) << 2;       // 0..28
    const int br = tid >> 4;             // 0..15 (2 row-passes of 16)
    const int bc = (tid & 15) << 2;      // 0..60

    float acc[2][4][4];
#pragma unroll
    for (int mi = 0; mi < 2; mi++)
#pragma unroll
        for (int ni = 0; ni < 4; ni++)
#pragma unroll
            for (int r = 0; r < 4; r++) acc[mi][ni][r] = 0.f;

    float4 aR[4], bR[2];

    // prefetch tile 0
#pragma unroll
    for (int p = 0; p < 4; p++)
        aR[p] = *reinterpret_cast<const float4*>(
            &A[(size_t)(m0 + ar + p * 32) * K + 0 + ac]);
#pragma unroll
    for (int p = 0; p < 2; p++)
        bR[p] = *reinterpret_cast<const float4*>(
            &Bm[(size_t)(0 + br + p * 16) * N + n0 + bc]);

    // store tile 0 (convert to tf32 once per element)
#pragma unroll
    for (int p = 0; p < 4; p++) {
        uint32_t* d = &As[ar + p * 32][ac];
        d[0] = f2tf(aR[p].x); d[1] = f2tf(aR[p].y);
        d[2] = f2tf(aR[p].z); d[3] = f2tf(aR[p].w);
    }
#pragma unroll
    for (int p = 0; p < 2; p++) {
        uint32_t* d = &Bs[br + p * 16][bc];
        d[0] = f2tf(bR[p].x); d[1] = f2tf(bR[p].y);
        d[2] = f2tf(bR[p].z); d[3] = f2tf(bR[p].w);
    }
    __syncthreads();

    const int KITERS = K / BK;           // 6
    for (int it = 0; it < KITERS; it++) {
        // prefetch next tile while this one computes
        if (it + 1 < KITERS) {
            const int k0 = (it + 1) * BK;
#pragma unroll
            for (int p = 0; p < 4; p++)
                aR[p] = *reinterpret_cast<const float4*>(
                    &A[(size_t)(m0 + ar + p * 32) * K + k0 + ac]);
#pragma unroll
            for (int p = 0; p < 2; p++)
                bR[p] = *reinterpret_cast<const float4*>(
                    &Bm[(size_t)(k0 + br + p * 16) * N + n0 + bc]);
        }

#pragma unroll
        for (int kk = 0; kk < BK; kk += 8) {
            uint32_t af[2][4], bf[4][2];
#pragma unroll
            for (int mi = 0; mi < 2; mi++) {
                const int r = wm + mi * 16 + gid;
                af[mi][0] = As[r][kk + tig];
                af[mi][1] = As[r + 8][kk + tig];
                af[mi][2] = As[r][kk + tig + 4];
                af[mi][3] = As[r + 8][kk + tig + 4];
            }
#pragma unroll
            for (int ni = 0; ni < 4; ni++) {
                const int c = wn + ni * 8 + gid;
                bf[ni][0] = Bs[kk + tig][c];
                bf[ni][1] = Bs[kk + tig + 4][c];
            }
#pragma unroll
            for (int mi = 0; mi < 2; mi++)
#pragma unroll
                for (int ni = 0; ni < 4; ni++)
                    mma_tf32(acc[mi][ni], af[mi], bf[ni]);
        }
        __syncthreads();

        if (it + 1 < KITERS) {
#pragma unroll
            for (int p = 0; p < 4; p++) {
                uint32_t* d = &As[ar + p * 32][ac];
                d[0] = f2tf(aR[p].x); d[1] = f2tf(aR[p].y);
                d[2] = f2tf(aR[p].z); d[3] = f2tf(aR[p].w);
            }
#pragma unroll
            for (int p = 0; p < 2; p++) {
                uint32_t* d = &Bs[br + p * 16][bc];
                d[0] = f2tf(bR[p].x); d[1] = f2tf(bR[p].y);
                d[2] = f2tf(bR[p].z); d[3] = f2tf(bR[p].w);
            }
            __syncthreads();
        }
    }

    // epilogue: bias add, float2 stores
#pragma unroll
    for (int mi = 0; mi < 2; mi++) {
#pragma unroll
        for (int ni = 0; ni < 4; ni++) {
            const int col = n0 + wn + ni * 8 + tig * 2;
            const float b0 = bias[col], b1 = bias[col + 1];
            const int r0 = m0 + wm + mi * 16 + gid;
            float2 v0 = make_float2(acc[mi][ni][0] + b0, acc[mi][ni][1] + b1);
            float2 v1 = make_float2(acc[mi][ni][2] + b0, acc[mi][ni][3] + b1);
            *reinterpret_cast<float2*>(&C[(size_t)r0 * N + col]) = v0;
            *reinterpret_cast<float2*>(&C[(size_t)(r0 + 8) * N + col]) = v1;
        }
    }
}

// ---------------------------------------------------------------------------
// Per-(window, head) attention. grid = (4096, 6), block = 64 threads.
// ---------------------------------------------------------------------------
__global__ __launch_bounds__(64) void attn_kernel(
    const float* __restrict__ mask,
    const float* __restrict__ bias_table)
{
    const int b = blockIdx.x;
    const int h = blockIdx.y;
    const int t = threadIdx.x;

    __shared__ float Ks[64][36];
    __shared__ float Vs[64][36];
    __shared__ float Ss[64][65];
    __shared__ float Bh[225];

    const float* base = g_qkv + (size_t)b * N_TOK * QKV_COLS;

    {
        const float* krow = base + t * QKV_COLS + C_DIM + h * D_HEAD;
        const float* vrow = base + t * QKV_COLS + 2 * C_DIM + h * D_HEAD;
#pragma unroll
        for (int d = 0; d < D_HEAD; d += 4) {
            *reinterpret_cast<float4*>(&Ks[t][d]) =
                *reinterpret_cast<const float4*>(krow + d);
            *reinterpret_cast<float4*>(&Vs[t][d]) =
                *reinterpret_cast<const float4*>(vrow + d);
        }
    }
    for (int i = t; i < 225; i += 64)
        Bh[i] = bias_table[i * H_NUM + h];

    float q[D_HEAD];
    {
        const float* qrow = base + t * QKV_COLS + h * D_HEAD;
#pragma unroll
        for (int d = 0; d < D_HEAD; d += 4) {
            float4 qv = *reinterpret_cast<const float4*>(qrow + d);
            q[d] = qv.x; q[d + 1] = qv.y; q[d + 2] = qv.z; q[d + 3] = qv.w;
        }
    }
    __syncthreads();

    const float* mrow = mask + (size_t)(((b & (NUM_WINS - 1)) * N_TOK + t) * N_TOK);
    const int ty = t >> 3, txp = t & 7;

    float mx = -1e30f;
#pragma unroll 4
    for (int j = 0; j < N_TOK; j++) {
        float dot = 0.f;
#pragma unroll
        for (int d = 0; d < D_HEAD; d += 4) {
            float4 kv = *reinterpret_cast<const float4*>(&Ks[j][d]);
            dot += q[d] * kv.x + q[d + 1] * kv.y + q[d + 2] * kv.z + q[d + 3] * kv.w;
        }
        const int idx = (ty - (j >> 3) + 7) * 15 + (txp - (j & 7) + 7);
        const float val = dot * QK_SCALE + Bh[idx] + mrow[j];
        Ss[t][j] = val;
        mx = fmaxf(mx, val);
    }

    float sum = 0.f;
#pragma unroll 8
    for (int j = 0; j < N_TOK; j++) {
        const float e = __expf(Ss[t][j] - mx);
        Ss[t][j] = e;
        sum += e;
    }
    const float inv = 1.f / sum;

    float o[D_HEAD];
#pragma unroll
    for (int d = 0; d < D_HEAD; d++) o[d] = 0.f;

#pragma unroll 4
    for (int j = 0; j < N_TOK; j++) {
        const float p = Ss[t][j];
#pragma unroll
        for (int d = 0; d < D_HEAD; d += 4) {
            float4 vv = *reinterpret_cast<const float4*>(&Vs[j][d]);
            o[d]     += p * vv.x;
            o[d + 1] += p * vv.y;
            o[d + 2] += p * vv.z;
            o[d + 3] += p * vv.w;
        }
    }

    float* orow = g_ctx + ((size_t)b * N_TOK + t) * C_DIM + h * D_HEAD;
#pragma unroll
    for (int d = 0; d < D_HEAD; d += 4) {
        float4 ov = make_float4(o[d] * inv, o[d + 1] * inv,
                                o[d + 2] * inv, o[d + 3] * inv);
        *reinterpret_cast<float4*>(orow + d) = ov;
    }
}

// ---------------------------------------------------------------------------
// Launch. Inputs: inputs, mask, w_qkv, b_qkv, bias_table, w_proj, b_proj
// ---------------------------------------------------------------------------
extern "C" void kernel_launch(void* const* d_in, const int* in_sizes, int n_in,
                              void* d_out, int out_size)
{
    const float* x          = (const float*)d_in[0];
    const float* mask       = (const float*)d_in[1];
    const float* w_qkv      = (const float*)d_in[2];
    const float* b_qkv      = (const float*)d_in[3];
    const float* bias_table = (const float*)d_in[4];
    const float* w_proj     = (const float*)d_in[5];
    const float* b_proj     = (const float*)d_in[6];
    float* out = (float*)d_out;

    float* qkv_ptr = nullptr;
    float* ctx_ptr = nullptr;
    cudaGetSymbolAddress((void**)&qkv_ptr, g_qkv);
    cudaGetSymbolAddress((void**)&ctx_ptr, g_ctx);

    const int M = B_WIN * N_TOK;          // 262144

    {   // K1: QKV projection  [M,192] @ [192,576]
        dim3 grid(QKV_COLS / BN, M / BM);
        gemm_tf32_kernel<<<grid, 256>>>(x, w_qkv, b_qkv, qkv_ptr,
                                        M, QKV_COLS, C_DIM);
    }
    {   // K2: attention
        dim3 grid(B_WIN, H_NUM);
        attn_kernel<<<grid, 64>>>(mask, bias_table);
    }
    {   // K3: output projection  [M,192] @ [192,192]
        dim3 grid(C_DIM / BN, M / BM);
        gemm_tf32_kernel<<<grid, 256>>>(ctx_ptr, w_proj, b_proj, out,
                                        M, C_DIM, C_DIM);
    }
}